// round 1
// baseline (speedup 1.0000x reference)
#include <cuda_runtime.h>
#include <math.h>

#define T_TOK 2048
#define H_DIM 2048
#define I_DIM 1408
#define NE    8
#define GS    128

// ---- scratch (static device arrays; no runtime allocation) ----
__device__ int   g_cnt[NE];
__device__ int   g_tok[NE * T_TOK];
__device__ float g_rw [NE * T_TOK];
__device__ float g_act[(size_t)NE * T_TOK * I_DIM];   // ~92 MB, only routed rows touched

// ---------------------------------------------------------------
// L0: zero output + expert counters
// ---------------------------------------------------------------
__global__ void zero_kernel(float* __restrict__ out, int n) {
    int i = blockIdx.x * blockDim.x + threadIdx.x;
    if (i < n) out[i] = 0.0f;
    if (i < NE) g_cnt[i] = 0;
}

// ---------------------------------------------------------------
// L1: routing — top-2 of 8, softmax over the two selected logits,
//     atomic compaction into per-expert lists.
// ---------------------------------------------------------------
__global__ void route_kernel(const float* __restrict__ logits) {
    int t = blockIdx.x * blockDim.x + threadIdx.x;
    if (t >= T_TOK) return;
    float v[NE];
#pragma unroll
    for (int e = 0; e < NE; ++e) v[e] = logits[t * NE + e];
    int i0 = 0;
#pragma unroll
    for (int e = 1; e < NE; ++e) if (v[e] > v[i0]) i0 = e;   // strict > => lowest index on tie (matches top_k)
    int i1 = (i0 == 0) ? 1 : 0;
#pragma unroll
    for (int e = 0; e < NE; ++e) if (e != i0 && v[e] > v[i1]) i1 = e;
    float ex = __expf(v[i1] - v[i0]);     // <= 0 exponent, safe
    float denom = 1.0f + ex;
    float w0 = 1.0f / denom;
    float w1 = ex / denom;
    int p0 = atomicAdd(&g_cnt[i0], 1);
    g_tok[i0 * T_TOK + p0] = t;  g_rw[i0 * T_TOK + p0] = w0;
    int p1 = atomicAdd(&g_cnt[i1], 1);
    g_tok[i1 * T_TOK + p1] = t;  g_rw[i1 * T_TOK + p1] = w1;
}

// ---------------------------------------------------------------
// L2: expert-grouped GEMM1 + fused SwiGLU.
// Block tile: BM=128 tokens x BN=64 I-features, computing BOTH the gate
// row (n) and up row (n + I) accumulators. BK=16, 256 threads, 8x4 regs.
// act[e_slot_row, n] = silu(gate) * up  (f32 scratch)
// ---------------------------------------------------------------
__global__ __launch_bounds__(256) void gemm1_kernel(
    const float* __restrict__ x,    // [T, H]
    const int*   __restrict__ qw,   // [E, 2I, H] int values 0..15
    const float* __restrict__ sc)   // [E, 2I, H/GS]
{
    const int e   = blockIdx.z;
    const int cnt = g_cnt[e];
    const int m0  = blockIdx.y * 128;
    if (m0 >= cnt) return;
    const int n0  = blockIdx.x * 64;

    __shared__ float sx[16][128];
    __shared__ float sg[16][64];
    __shared__ float su[16][64];

    const int tid = threadIdx.x;
    const int tx  = tid & 15;   // n direction (x4)
    const int ty  = tid >> 4;   // m direction (x8)

    float accg[8][4], accu[8][4];
#pragma unroll
    for (int i = 0; i < 8; ++i)
#pragma unroll
        for (int j = 0; j < 4; ++j) { accg[i][j] = 0.0f; accu[i][j] = 0.0f; }

    const int* tokp = g_tok + e * T_TOK;

    for (int k0 = 0; k0 < H_DIM; k0 += 16) {
        // --- load x tile: 128 rows x 16 k = 512 float4, 2 per thread ---
#pragma unroll
        for (int l = 0; l < 2; ++l) {
            int idx = tid + l * 256;
            int row = idx >> 2;
            int kq  = idx & 3;
            float4 v = make_float4(0.f, 0.f, 0.f, 0.f);
            int m = m0 + row;
            if (m < cnt) {
                int tok = tokp[m];
                v = *reinterpret_cast<const float4*>(x + (size_t)tok * H_DIM + k0 + kq * 4);
            }
            sx[kq * 4 + 0][row] = v.x;
            sx[kq * 4 + 1][row] = v.y;
            sx[kq * 4 + 2][row] = v.z;
            sx[kq * 4 + 3][row] = v.w;
        }
        // --- load gate (tile 0) + up (tile 1) weights, dequant to smem ---
        const int kg = k0 >> 7;   // scale group along H
#pragma unroll
        for (int l = 0; l < 2; ++l) {
            int idx  = tid + l * 256;      // l==0 -> gate tile, l==1 -> up tile
            int rr   = (idx >> 2) & 63;
            int kq   = idx & 3;
            int nrow = n0 + rr + l * I_DIM;
            const int4 q = *reinterpret_cast<const int4*>(
                qw + ((size_t)e * 2 * I_DIM + nrow) * H_DIM + k0 + kq * 4);
            float s = sc[((size_t)e * 2 * I_DIM + nrow) * (H_DIM / GS) + kg];
            float f0 = (float)(q.x - 8) * s;
            float f1 = (float)(q.y - 8) * s;
            float f2 = (float)(q.z - 8) * s;
            float f3 = (float)(q.w - 8) * s;
            if (l == 0) {
                sg[kq * 4 + 0][rr] = f0; sg[kq * 4 + 1][rr] = f1;
                sg[kq * 4 + 2][rr] = f2; sg[kq * 4 + 3][rr] = f3;
            } else {
                su[kq * 4 + 0][rr] = f0; su[kq * 4 + 1][rr] = f1;
                su[kq * 4 + 2][rr] = f2; su[kq * 4 + 3][rr] = f3;
            }
        }
        __syncthreads();

#pragma unroll
        for (int k = 0; k < 16; ++k) {
            float4 a0 = *reinterpret_cast<const float4*>(&sx[k][ty * 8]);
            float4 a1 = *reinterpret_cast<const float4*>(&sx[k][ty * 8 + 4]);
            float  a[8] = {a0.x, a0.y, a0.z, a0.w, a1.x, a1.y, a1.z, a1.w};
            float4 bgv = *reinterpret_cast<const float4*>(&sg[k][tx * 4]);
            float4 buv = *reinterpret_cast<const float4*>(&su[k][tx * 4]);
            float bg[4] = {bgv.x, bgv.y, bgv.z, bgv.w};
            float bu[4] = {buv.x, buv.y, buv.z, buv.w};
#pragma unroll
            for (int i = 0; i < 8; ++i)
#pragma unroll
                for (int j = 0; j < 4; ++j) {
                    accg[i][j] += a[i] * bg[j];
                    accu[i][j] += a[i] * bu[j];
                }
        }
        __syncthreads();
    }

    // --- epilogue: SwiGLU -> act scratch ---
#pragma unroll
    for (int i = 0; i < 8; ++i) {
        int m = m0 + ty * 8 + i;
        if (m >= cnt) continue;
        float* arow = g_act + ((size_t)e * T_TOK + m) * I_DIM + n0 + tx * 4;
#pragma unroll
        for (int j = 0; j < 4; ++j) {
            float g = accg[i][j];
            float u = accu[i][j];
            float sig = 1.0f / (1.0f + __expf(-g));
            arow[j] = g * sig * u;
        }
    }
}

// ---------------------------------------------------------------
// L3: expert-grouped GEMM2 (act @ w_down^T), scale by routing weight,
// atomicAdd scatter to out[tok, h]. Exactly 2 adds per element ->
// commutative fp32 -> deterministic.
// ---------------------------------------------------------------
__global__ __launch_bounds__(256) void gemm2_kernel(
    const int*   __restrict__ qw,   // [E, H, I]
    const float* __restrict__ sc,   // [E, H, I/GS]
    float*       __restrict__ out)  // [T, H]
{
    const int e   = blockIdx.z;
    const int cnt = g_cnt[e];
    const int m0  = blockIdx.y * 128;
    if (m0 >= cnt) return;
    const int n0  = blockIdx.x * 64;   // H features

    __shared__ float sa[16][128];
    __shared__ float sb[16][64];

    const int tid = threadIdx.x;
    const int tx  = tid & 15;
    const int ty  = tid >> 4;

    float acc[8][4];
#pragma unroll
    for (int i = 0; i < 8; ++i)
#pragma unroll
        for (int j = 0; j < 4; ++j) acc[i][j] = 0.0f;

    for (int k0 = 0; k0 < I_DIM; k0 += 16) {
        // --- act tile: 512 float4, 2 per thread ---
#pragma unroll
        for (int l = 0; l < 2; ++l) {
            int idx = tid + l * 256;
            int row = idx >> 2;
            int kq  = idx & 3;
            float4 v = make_float4(0.f, 0.f, 0.f, 0.f);
            int m = m0 + row;
            if (m < cnt) {
                v = *reinterpret_cast<const float4*>(
                    g_act + ((size_t)e * T_TOK + m) * I_DIM + k0 + kq * 4);
            }
            sa[kq * 4 + 0][row] = v.x;
            sa[kq * 4 + 1][row] = v.y;
            sa[kq * 4 + 2][row] = v.z;
            sa[kq * 4 + 3][row] = v.w;
        }
        // --- down weight tile: 64 rows x 16 k = 256 int4, 1 per thread ---
        {
            int rr = tid >> 2;
            int kq = tid & 3;
            int h  = n0 + rr;
            const int4 q = *reinterpret_cast<const int4*>(
                qw + ((size_t)e * H_DIM + h) * I_DIM + k0 + kq * 4);
            float s = sc[((size_t)e * H_DIM + h) * (I_DIM / GS) + (k0 >> 7)];
            sb[kq * 4 + 0][rr] = (float)(q.x - 8) * s;
            sb[kq * 4 + 1][rr] = (float)(q.y - 8) * s;
            sb[kq * 4 + 2][rr] = (float)(q.z - 8) * s;
            sb[kq * 4 + 3][rr] = (float)(q.w - 8) * s;
        }
        __syncthreads();

#pragma unroll
        for (int k = 0; k < 16; ++k) {
            float4 a0 = *reinterpret_cast<const float4*>(&sa[k][ty * 8]);
            float4 a1 = *reinterpret_cast<const float4*>(&sa[k][ty * 8 + 4]);
            float  a[8] = {a0.x, a0.y, a0.z, a0.w, a1.x, a1.y, a1.z, a1.w};
            float4 bv = *reinterpret_cast<const float4*>(&sb[k][tx * 4]);
            float  b[4] = {bv.x, bv.y, bv.z, bv.w};
#pragma unroll
            for (int i = 0; i < 8; ++i)
#pragma unroll
                for (int j = 0; j < 4; ++j)
                    acc[i][j] += a[i] * b[j];
        }
        __syncthreads();
    }

    // --- epilogue: scale by route weight, scatter-add ---
#pragma unroll
    for (int i = 0; i < 8; ++i) {
        int m = m0 + ty * 8 + i;
        if (m >= cnt) continue;
        int   tok = g_tok[e * T_TOK + m];
        float rw  = g_rw [e * T_TOK + m];
        float* orow = out + (size_t)tok * H_DIM + n0 + tx * 4;
#pragma unroll
        for (int j = 0; j < 4; ++j)
            atomicAdd(&orow[j], rw * acc[i][j]);
    }
}

// ---------------------------------------------------------------
// kernel_launch: 4 graph-capturable launches, no sync, no alloc
// ---------------------------------------------------------------
extern "C" void kernel_launch(void* const* d_in, const int* in_sizes, int n_in,
                              void* d_out, int out_size) {
    const float* logits = (const float*)d_in[0];   // [2,1024,8]
    const float* x      = (const float*)d_in[1];   // [2,1024,2048]
    const int*   qgu    = (const int*)  d_in[2];   // [8,2816,2048]
    const float* sgu    = (const float*)d_in[3];   // [8,2816,16]
    const int*   qd     = (const int*)  d_in[4];   // [8,2048,1408]
    const float* sd     = (const float*)d_in[5];   // [8,2048,11]
    float* out = (float*)d_out;                    // [2,1024,2048] f32

    const int n_out = T_TOK * H_DIM;
    zero_kernel<<<(n_out + 255) / 256, 256>>>(out, n_out);
    route_kernel<<<(T_TOK + 127) / 128, 128>>>(logits);

    dim3 g1(I_DIM / 64, T_TOK / 128, NE);   // (22, 16, 8)
    gemm1_kernel<<<g1, 256>>>(x, qgu, sgu);

    dim3 g2(H_DIM / 64, T_TOK / 128, NE);   // (32, 16, 8)
    gemm2_kernel<<<g2, 256>>>(qd, sd, out);
}

// round 3
// speedup vs baseline: 2.5060x; 2.5060x over previous
#include <cuda_runtime.h>
#include <cuda_fp16.h>
#include <stdint.h>
#include <string.h>

#define T_TOK 2048
#define H_DIM 2048
#define I_DIM 1408
#define NE    8
#define GS    128
#define NG1   (H_DIM / GS)   // 16
#define NG2   (I_DIM / GS)   // 11
#define BM    128
#define BK    32
#define LDSW  40             // padded smem row stride in fp16 elems (80B)

// ---- scratch ----
__device__ int    g_cnt[NE];
__device__ int    g_tok[NE * T_TOK];
__device__ float  g_rw [NE * T_TOK];
__device__ __half g_act[(size_t)NE * T_TOK * I_DIM];   // fp16 act scratch (~46 MB)

// ---------------- helpers ----------------
__device__ __forceinline__ uint32_t h2u(__half2 h) {
    uint32_t u;
    memcpy(&u, &h, 4);
    return u;
}
__device__ __forceinline__ uint32_t smem_u32(const void* p) {
    uint32_t a;
    asm("{ .reg .u64 t; cvta.to.shared.u64 t, %1; cvt.u32.u64 %0, t; }"
        : "=r"(a) : "l"(p));
    return a;
}
__device__ __forceinline__ void ldm_x4(uint32_t* r, uint32_t addr) {
    asm volatile("ldmatrix.sync.aligned.m8n8.x4.shared.b16 {%0,%1,%2,%3}, [%4];"
        : "=r"(r[0]), "=r"(r[1]), "=r"(r[2]), "=r"(r[3]) : "r"(addr));
}
__device__ __forceinline__ void mma16816(float* d, const uint32_t* a, const uint32_t* b) {
    asm volatile("mma.sync.aligned.m16n8k16.row.col.f32.f16.f16.f32 "
        "{%0,%1,%2,%3}, {%4,%5,%6,%7}, {%8,%9}, {%0,%1,%2,%3};"
        : "+f"(d[0]), "+f"(d[1]), "+f"(d[2]), "+f"(d[3])
        : "r"(a[0]), "r"(a[1]), "r"(a[2]), "r"(a[3]), "r"(b[0]), "r"(b[1]));
}

// ---------------- L0: zero output + counters ----------------
__global__ void zero_kernel(float* __restrict__ out, int n) {
    int i = blockIdx.x * blockDim.x + threadIdx.x;
    if (i < n) out[i] = 0.0f;
    if (i < NE) g_cnt[i] = 0;
}

// ---------------- L1: routing ----------------
__global__ void route_kernel(const float* __restrict__ logits) {
    int t = blockIdx.x * blockDim.x + threadIdx.x;
    if (t >= T_TOK) return;
    float v[NE];
#pragma unroll
    for (int e = 0; e < NE; ++e) v[e] = logits[t * NE + e];
    int i0 = 0;
#pragma unroll
    for (int e = 1; e < NE; ++e) if (v[e] > v[i0]) i0 = e;
    int i1 = (i0 == 0) ? 1 : 0;
#pragma unroll
    for (int e = 0; e < NE; ++e) if (e != i0 && v[e] > v[i1]) i1 = e;
    float ex = __expf(v[i1] - v[i0]);
    float w0 = 1.0f / (1.0f + ex);
    float w1 = ex * w0;
    int p0 = atomicAdd(&g_cnt[i0], 1);
    g_tok[i0 * T_TOK + p0] = t;  g_rw[i0 * T_TOK + p0] = w0;
    int p1 = atomicAdd(&g_cnt[i1], 1);
    g_tok[i1 * T_TOK + p1] = t;  g_rw[i1 * T_TOK + p1] = w1;
}

// =================================================================
// GEMM1: x[fp16] @ Wgate/Wup[int4 exact fp16], per-group fp32 scale,
// fused SwiGLU -> g_act (fp16).
// Block: 128m x (32 gate + 32 up) x BK=32.  8 warps: 4(m) x 2(n).
// grid: (mtiles=16, ntiles=44, E)  -- m fastest for weight-L2 reuse
// =================================================================
__global__ __launch_bounds__(256, 2) void gemm1_kernel(
    const float* __restrict__ x,
    const int*   __restrict__ qw,
    const float* __restrict__ sc)
{
    const int e   = blockIdx.z;
    const int cnt = g_cnt[e];
    const int m0  = blockIdx.x * BM;
    if (m0 >= cnt) return;
    const int n0  = blockIdx.y * 32;

    __shared__ __half sx[BM * LDSW];
    __shared__ __half sg[32 * LDSW];
    __shared__ __half su[32 * LDSW];
    __shared__ float  ssc[64 * NG1];

    const int tid    = threadIdx.x;
    const int lane   = tid & 31;
    const int wid    = tid >> 5;
    const int warp_m = wid & 3;    // 32 rows each
    const int warp_n = wid >> 2;   // 16 cols each (per half)

    // preload this block's scales: rows 0..31 gate(n0+), 32..63 up(I+n0+)
#pragma unroll
    for (int i = tid; i < 64 * NG1; i += 256) {
        int row = i >> 4;
        int g   = i & 15;
        int nrow = (row < 32) ? (n0 + row) : (I_DIM + n0 + row - 32);
        ssc[i] = sc[((size_t)e * 2 * I_DIM + nrow) * NG1 + g];
    }

    float pg[2][2][4], fg[2][2][4], pu[2][2][4], fu[2][2][4];
#pragma unroll
    for (int a = 0; a < 2; ++a)
#pragma unroll
        for (int b = 0; b < 2; ++b)
#pragma unroll
            for (int c = 0; c < 4; ++c) {
                pg[a][b][c] = 0.f; fg[a][b][c] = 0.f;
                pu[a][b][c] = 0.f; fu[a][b][c] = 0.f;
            }

    const int* tokp = g_tok + e * T_TOK;
    // per-thread global-load coords
    const int xr  = tid >> 1;            // 0..127
    const int xk  = (tid & 1) * 16;
    const int tokr = (m0 + xr < cnt) ? tokp[m0 + xr] : -1;
    const int wr  = tid >> 3;            // 0..31
    const int wk  = (tid & 7) * 4;

    // ldmatrix per-thread smem offsets (bytes), kk added per step
    const uint32_t sx_base = smem_u32(sx);
    const uint32_t sg_base = smem_u32(sg);
    const uint32_t su_base = smem_u32(su);
    uint32_t a_off[2];
#pragma unroll
    for (int mf = 0; mf < 2; ++mf) {
        int ar = warp_m * 32 + mf * 16 + (lane & 15);
        a_off[mf] = (uint32_t)((ar * LDSW + (lane >> 4) * 8) * 2);
    }
    const int brow  = (lane & 7) + ((lane >> 4) << 3);
    const int bcol  = ((lane >> 3) & 1) * 8;
    const uint32_t b_off = (uint32_t)(((warp_n * 16 + brow) * LDSW + bcol) * 2);

    for (int kb = 0; kb < H_DIM; kb += BK) {
        // ---- x tile: 128 x 32 fp32 -> fp16 ----
        {
            uint32_t u[8];
            if (tokr >= 0) {
                const float4* src = (const float4*)(x + (size_t)tokr * H_DIM + kb + xk);
#pragma unroll
                for (int q = 0; q < 4; ++q) {
                    float4 v = src[q];
                    u[q * 2 + 0] = h2u(__floats2half2_rn(v.x, v.y));
                    u[q * 2 + 1] = h2u(__floats2half2_rn(v.z, v.w));
                }
            } else {
#pragma unroll
                for (int q = 0; q < 8; ++q) u[q] = 0u;
            }
            uint4* dst = (uint4*)&sx[xr * LDSW + xk];
            dst[0] = make_uint4(u[0], u[1], u[2], u[3]);
            dst[1] = make_uint4(u[4], u[5], u[6], u[7]);
        }
        // ---- gate weights 32 x 32 ----
        {
            const int4 q = *(const int4*)(qw + ((size_t)e * 2 * I_DIM + n0 + wr) * H_DIM + kb + wk);
            uint32_t u0 = h2u(__floats2half2_rn((float)(q.x - 8), (float)(q.y - 8)));
            uint32_t u1 = h2u(__floats2half2_rn((float)(q.z - 8), (float)(q.w - 8)));
            *(uint2*)&sg[wr * LDSW + wk] = make_uint2(u0, u1);
        }
        // ---- up weights 32 x 32 ----
        {
            const int4 q = *(const int4*)(qw + ((size_t)e * 2 * I_DIM + I_DIM + n0 + wr) * H_DIM + kb + wk);
            uint32_t u0 = h2u(__floats2half2_rn((float)(q.x - 8), (float)(q.y - 8)));
            uint32_t u1 = h2u(__floats2half2_rn((float)(q.z - 8), (float)(q.w - 8)));
            *(uint2*)&su[wr * LDSW + wk] = make_uint2(u0, u1);
        }
        __syncthreads();

#pragma unroll
        for (int ks = 0; ks < 2; ++ks) {
            const uint32_t kkb = (uint32_t)(ks * 16 * 2);
            uint32_t A[2][4], Bg[4], Bu[4];
            ldm_x4(A[0], sx_base + a_off[0] + kkb);
            ldm_x4(A[1], sx_base + a_off[1] + kkb);
            ldm_x4(Bg, sg_base + b_off + kkb);
            ldm_x4(Bu, su_base + b_off + kkb);
#pragma unroll
            for (int mf = 0; mf < 2; ++mf)
#pragma unroll
                for (int nf = 0; nf < 2; ++nf) {
                    mma16816(pg[mf][nf], A[mf], &Bg[nf * 2]);
                    mma16816(pu[mf][nf], A[mf], &Bu[nf * 2]);
                }
        }
        __syncthreads();

        if (((kb + BK) & 127) == 0) {   // group boundary: apply fp32 scales
            const int g = kb >> 7;
#pragma unroll
            for (int nf = 0; nf < 2; ++nf) {
                const int c0 = warp_n * 16 + nf * 8 + (lane & 3) * 2;
                const float sg0 = ssc[c0 * NG1 + g];
                const float sg1 = ssc[(c0 + 1) * NG1 + g];
                const float su0 = ssc[(32 + c0) * NG1 + g];
                const float su1 = ssc[(33 + c0) * NG1 + g];
#pragma unroll
                for (int mf = 0; mf < 2; ++mf) {
                    fg[mf][nf][0] += sg0 * pg[mf][nf][0]; pg[mf][nf][0] = 0.f;
                    fg[mf][nf][1] += sg1 * pg[mf][nf][1]; pg[mf][nf][1] = 0.f;
                    fg[mf][nf][2] += sg0 * pg[mf][nf][2]; pg[mf][nf][2] = 0.f;
                    fg[mf][nf][3] += sg1 * pg[mf][nf][3]; pg[mf][nf][3] = 0.f;
                    fu[mf][nf][0] += su0 * pu[mf][nf][0]; pu[mf][nf][0] = 0.f;
                    fu[mf][nf][1] += su1 * pu[mf][nf][1]; pu[mf][nf][1] = 0.f;
                    fu[mf][nf][2] += su0 * pu[mf][nf][2]; pu[mf][nf][2] = 0.f;
                    fu[mf][nf][3] += su1 * pu[mf][nf][3]; pu[mf][nf][3] = 0.f;
                }
            }
        }
    }

    // ---- epilogue: SwiGLU -> g_act fp16 ----
#pragma unroll
    for (int mf = 0; mf < 2; ++mf) {
#pragma unroll
        for (int nf = 0; nf < 2; ++nf) {
            const int r0 = warp_m * 32 + mf * 16 + (lane >> 2);
            const int c0 = warp_n * 16 + nf * 8 + (lane & 3) * 2;
#pragma unroll
            for (int half_row = 0; half_row < 2; ++half_row) {
                const int m = m0 + r0 + half_row * 8;
                if (m >= cnt) continue;
                const float gv0 = fg[mf][nf][half_row * 2 + 0];
                const float gv1 = fg[mf][nf][half_row * 2 + 1];
                const float uv0 = fu[mf][nf][half_row * 2 + 0];
                const float uv1 = fu[mf][nf][half_row * 2 + 1];
                const float a0 = gv0 / (1.0f + __expf(-gv0)) * uv0;
                const float a1 = gv1 / (1.0f + __expf(-gv1)) * uv1;
                *(__half2*)&g_act[((size_t)e * T_TOK + m) * I_DIM + n0 + c0] =
                    __floats2half2_rn(a0, a1);
            }
        }
    }
}

// =================================================================
// GEMM2: act[fp16] @ Wdown[int4 exact], per-group fp32 scale,
// route-weighted atomicAdd to out.
// Block: 128m x 64n x 32k.  8 warps: 4(m) x 2(n: 32 cols = 4 frags).
// grid: (mtiles=16, ntiles=32, E)
// =================================================================
__global__ __launch_bounds__(256, 2) void gemm2_kernel(
    const int*   __restrict__ qw,
    const float* __restrict__ sc,
    float*       __restrict__ out)
{
    const int e   = blockIdx.z;
    const int cnt = g_cnt[e];
    const int m0  = blockIdx.x * BM;
    if (m0 >= cnt) return;
    const int n0  = blockIdx.y * 64;

    __shared__ __half sa[BM * LDSW];
    __shared__ __half sw[64 * LDSW];
    __shared__ float  ssc[64 * NG2];

    const int tid    = threadIdx.x;
    const int lane   = tid & 31;
    const int wid    = tid >> 5;
    const int warp_m = wid & 3;
    const int warp_n = wid >> 2;   // 32 cols each

#pragma unroll
    for (int i = tid; i < 64 * NG2; i += 256) {
        int row = i / NG2;
        int g   = i - row * NG2;
        ssc[i] = sc[((size_t)e * H_DIM + n0 + row) * NG2 + g];
    }

    float pa[2][4][4], fa[2][4][4];
#pragma unroll
    for (int a = 0; a < 2; ++a)
#pragma unroll
        for (int b = 0; b < 4; ++b)
#pragma unroll
            for (int c = 0; c < 4; ++c) { pa[a][b][c] = 0.f; fa[a][b][c] = 0.f; }

    const int ar  = tid >> 1;
    const int ak  = (tid & 1) * 16;
    const bool a_ok = (m0 + ar) < cnt;
    const int wr  = tid >> 2;            // 0..63
    const int wk  = (tid & 3) * 8;

    const uint32_t sa_base = smem_u32(sa);
    const uint32_t sw_base = smem_u32(sw);
    uint32_t a_off[2];
#pragma unroll
    for (int mf = 0; mf < 2; ++mf) {
        int r = warp_m * 32 + mf * 16 + (lane & 15);
        a_off[mf] = (uint32_t)((r * LDSW + (lane >> 4) * 8) * 2);
    }
    const int brow = (lane & 7) + ((lane >> 4) << 3);
    const int bcol = ((lane >> 3) & 1) * 8;
    uint32_t b_off[2];
#pragma unroll
    for (int bb = 0; bb < 2; ++bb)
        b_off[bb] = (uint32_t)(((warp_n * 32 + bb * 16 + brow) * LDSW + bcol) * 2);

    for (int kb = 0; kb < I_DIM; kb += BK) {
        // ---- act tile 128 x 32 fp16 ----
        {
            uint4 v0, v1;
            if (a_ok) {
                const uint4* src = (const uint4*)(g_act + ((size_t)e * T_TOK + m0 + ar) * I_DIM + kb + ak);
                v0 = src[0]; v1 = src[1];
            } else {
                v0 = make_uint4(0, 0, 0, 0); v1 = v0;
            }
            uint4* dst = (uint4*)&sa[ar * LDSW + ak];
            dst[0] = v0; dst[1] = v1;
        }
        // ---- down weights 64 x 32 ----
        {
            const int4* src = (const int4*)(qw + ((size_t)e * H_DIM + n0 + wr) * I_DIM + kb + wk);
            const int4 q0 = src[0];
            const int4 q1 = src[1];
            uint32_t u0 = h2u(__floats2half2_rn((float)(q0.x - 8), (float)(q0.y - 8)));
            uint32_t u1 = h2u(__floats2half2_rn((float)(q0.z - 8), (float)(q0.w - 8)));
            uint32_t u2 = h2u(__floats2half2_rn((float)(q1.x - 8), (float)(q1.y - 8)));
            uint32_t u3 = h2u(__floats2half2_rn((float)(q1.z - 8), (float)(q1.w - 8)));
            uint4* dst = (uint4*)&sw[wr * LDSW + wk];
            dst[0] = make_uint4(u0, u1, u2, u3);
        }
        __syncthreads();

#pragma unroll
        for (int ks = 0; ks < 2; ++ks) {
            const uint32_t kkb = (uint32_t)(ks * 16 * 2);
            uint32_t A[2][4], B[2][4];
            ldm_x4(A[0], sa_base + a_off[0] + kkb);
            ldm_x4(A[1], sa_base + a_off[1] + kkb);
            ldm_x4(B[0], sw_base + b_off[0] + kkb);
            ldm_x4(B[1], sw_base + b_off[1] + kkb);
#pragma unroll
            for (int mf = 0; mf < 2; ++mf)
#pragma unroll
                for (int nf = 0; nf < 4; ++nf)
                    mma16816(pa[mf][nf], A[mf], &B[nf >> 1][(nf & 1) * 2]);
        }
        __syncthreads();

        if (((kb + BK) & 127) == 0) {
            const int g = kb >> 7;
#pragma unroll
            for (int nf = 0; nf < 4; ++nf) {
                const int c0 = warp_n * 32 + nf * 8 + (lane & 3) * 2;
                const float s0 = ssc[c0 * NG2 + g];
                const float s1 = ssc[(c0 + 1) * NG2 + g];
#pragma unroll
                for (int mf = 0; mf < 2; ++mf) {
                    fa[mf][nf][0] += s0 * pa[mf][nf][0]; pa[mf][nf][0] = 0.f;
                    fa[mf][nf][1] += s1 * pa[mf][nf][1]; pa[mf][nf][1] = 0.f;
                    fa[mf][nf][2] += s0 * pa[mf][nf][2]; pa[mf][nf][2] = 0.f;
                    fa[mf][nf][3] += s1 * pa[mf][nf][3]; pa[mf][nf][3] = 0.f;
                }
            }
        }
    }

    // ---- epilogue: route-weighted scatter-add ----
#pragma unroll
    for (int mf = 0; mf < 2; ++mf) {
#pragma unroll
        for (int half_row = 0; half_row < 2; ++half_row) {
            const int r = warp_m * 32 + mf * 16 + (lane >> 2) + half_row * 8;
            const int m = m0 + r;
            if (m >= cnt) continue;
            const int   tok = g_tok[e * T_TOK + m];
            const float rw  = g_rw [e * T_TOK + m];
            float* orow = out + (size_t)tok * H_DIM;
#pragma unroll
            for (int nf = 0; nf < 4; ++nf) {
                const int c0 = n0 + warp_n * 32 + nf * 8 + (lane & 3) * 2;
                atomicAdd(&orow[c0],     rw * fa[mf][nf][half_row * 2 + 0]);
                atomicAdd(&orow[c0 + 1], rw * fa[mf][nf][half_row * 2 + 1]);
            }
        }
    }
}

// ---------------------------------------------------------------
extern "C" void kernel_launch(void* const* d_in, const int* in_sizes, int n_in,
                              void* d_out, int out_size) {
    const float* logits = (const float*)d_in[0];
    const float* x      = (const float*)d_in[1];
    const int*   qgu    = (const int*)  d_in[2];
    const float* sgu    = (const float*)d_in[3];
    const int*   qd     = (const int*)  d_in[4];
    const float* sd     = (const float*)d_in[5];
    float* out = (float*)d_out;

    const int n_out = T_TOK * H_DIM;
    zero_kernel<<<(n_out + 255) / 256, 256>>>(out, n_out);
    route_kernel<<<(T_TOK + 127) / 128, 128>>>(logits);

    dim3 g1(T_TOK / BM, I_DIM / 32, NE);   // (16, 44, 8), m fastest
    gemm1_kernel<<<g1, 256>>>(x, qgu, sgu);

    dim3 g2(T_TOK / BM, H_DIM / 64, NE);   // (16, 32, 8)
    gemm2_kernel<<<g2, 256>>>(qd, sd, out);
}

// round 4
// speedup vs baseline: 5.9744x; 2.3840x over previous
#include <cuda_runtime.h>
#include <cuda_fp16.h>
#include <stdint.h>
#include <string.h>

#define T_TOK 2048
#define H_DIM 2048
#define I_DIM 1408
#define NE    8
#define GS    128
#define BM    128
#define BK    64
#define LDSW  72                      // smem row stride in halves (144B)
#define A_OFF (128 * LDSW)            // placeholder (A at 0, B at A_OFF)
#define STAGE_HALVES (2 * 128 * LDSW) // A tile + B tile per stage
#define SMEM_BYTES (2 * STAGE_HALVES * 2)  // 2 stages, fp16 -> 73728 B

// ---- persistent device scratch (no runtime allocation) ----
__device__ int    g_cnt[NE];
__device__ int    g_tok[NE * T_TOK];
__device__ float  g_rw [NE * T_TOK];
__device__ __half g_x  [(size_t)T_TOK * H_DIM];
__device__ __half g_act[(size_t)NE * T_TOK * I_DIM];
__device__ __half g_wgu[(size_t)NE * 2 * I_DIM * H_DIM];  // 92 MB fp16 dequant
__device__ __half g_wd [(size_t)NE * H_DIM * I_DIM];      // 46 MB fp16 dequant

// ---------------- helpers ----------------
__device__ __forceinline__ uint32_t h2u(__half2 h) {
    uint32_t u; memcpy(&u, &h, 4); return u;
}
__device__ __forceinline__ uint32_t smem_u32(const void* p) {
    uint32_t a;
    asm("{ .reg .u64 t; cvta.to.shared.u64 t, %1; cvt.u32.u64 %0, t; }"
        : "=r"(a) : "l"(p));
    return a;
}
__device__ __forceinline__ void ldm_x4(uint32_t* r, uint32_t addr) {
    asm volatile("ldmatrix.sync.aligned.m8n8.x4.shared.b16 {%0,%1,%2,%3}, [%4];"
        : "=r"(r[0]), "=r"(r[1]), "=r"(r[2]), "=r"(r[3]) : "r"(addr));
}
__device__ __forceinline__ void mma16816(float* d, const uint32_t* a, const uint32_t* b) {
    asm volatile("mma.sync.aligned.m16n8k16.row.col.f32.f16.f16.f32 "
        "{%0,%1,%2,%3}, {%4,%5,%6,%7}, {%8,%9}, {%0,%1,%2,%3};"
        : "+f"(d[0]), "+f"(d[1]), "+f"(d[2]), "+f"(d[3])
        : "r"(a[0]), "r"(a[1]), "r"(a[2]), "r"(a[3]), "r"(b[0]), "r"(b[1]));
}
__device__ __forceinline__ void cp16(uint32_t dst, const void* src) {
    asm volatile("cp.async.cg.shared.global [%0], [%1], 16;" :: "r"(dst), "l"(src));
}
#define CP_COMMIT()  asm volatile("cp.async.commit_group;")
#define CP_WAIT(n)   asm volatile("cp.async.wait_group %0;" :: "n"(n))

// ---------------- L0: zero output + counters ----------------
__global__ void zero_kernel(float* __restrict__ out, int n) {
    int i = blockIdx.x * blockDim.x + threadIdx.x;
    if (i < n) out[i] = 0.0f;
    if (i < NE) g_cnt[i] = 0;
}

// ---------------- L1: routing ----------------
__global__ void route_kernel(const float* __restrict__ logits) {
    int t = blockIdx.x * blockDim.x + threadIdx.x;
    if (t >= T_TOK) return;
    float v[NE];
#pragma unroll
    for (int e = 0; e < NE; ++e) v[e] = logits[t * NE + e];
    int i0 = 0;
#pragma unroll
    for (int e = 1; e < NE; ++e) if (v[e] > v[i0]) i0 = e;
    int i1 = (i0 == 0) ? 1 : 0;
#pragma unroll
    for (int e = 0; e < NE; ++e) if (e != i0 && v[e] > v[i1]) i1 = e;
    float ex = __expf(v[i1] - v[i0]);
    float w0 = 1.0f / (1.0f + ex);
    float w1 = ex * w0;
    int p0 = atomicAdd(&g_cnt[i0], 1);
    g_tok[i0 * T_TOK + p0] = t;  g_rw[i0 * T_TOK + p0] = w0;
    int p1 = atomicAdd(&g_cnt[i1], 1);
    g_tok[i1 * T_TOK + p1] = t;  g_rw[i1 * T_TOK + p1] = w1;
}

// ---------------- L2: x fp32 -> fp16 ----------------
__global__ void convert_x_kernel(const float* __restrict__ x) {
    size_t i = ((size_t)blockIdx.x * 256 + threadIdx.x) * 8;
    float4 a = *(const float4*)(x + i);
    float4 b = *(const float4*)(x + i + 4);
    uint4 o;
    o.x = h2u(__floats2half2_rn(a.x, a.y));
    o.y = h2u(__floats2half2_rn(a.z, a.w));
    o.z = h2u(__floats2half2_rn(b.x, b.y));
    o.w = h2u(__floats2half2_rn(b.z, b.w));
    *(uint4*)(g_x + i) = o;
}

// ---------------- L3: dequant gate_up weights -> fp16 (scale folded) ----------------
__global__ void dequant_gu_kernel(const int* __restrict__ q, const float* __restrict__ s) {
    int gid = blockIdx.x * 256 + threadIdx.x;           // 2,883,584 threads
    int row = gid >> 7;                                  // [0, 8*2816)
    int kc  = (gid & 127) << 4;                          // 16 elems per thread
    const int4* src = (const int4*)(q + (size_t)row * H_DIM + kc);
    float sc = s[row * (H_DIM / GS) + (kc >> 7)];
    uint32_t o[8];
#pragma unroll
    for (int j = 0; j < 4; ++j) {
        int4 v = src[j];
        o[j * 2 + 0] = h2u(__floats2half2_rn(sc * (float)(v.x - 8), sc * (float)(v.y - 8)));
        o[j * 2 + 1] = h2u(__floats2half2_rn(sc * (float)(v.z - 8), sc * (float)(v.w - 8)));
    }
    uint4* dst = (uint4*)(g_wgu + (size_t)row * H_DIM + kc);
    dst[0] = make_uint4(o[0], o[1], o[2], o[3]);
    dst[1] = make_uint4(o[4], o[5], o[6], o[7]);
}

// ---------------- L4: dequant down weights -> fp16 ----------------
__global__ void dequant_dn_kernel(const int* __restrict__ q, const float* __restrict__ s) {
    int gid = blockIdx.x * 256 + threadIdx.x;           // 1,441,792 threads
    int row = gid / 88;                                  // [0, 8*2048)
    int kc  = (gid - row * 88) << 4;
    const int4* src = (const int4*)(q + (size_t)row * I_DIM + kc);
    float sc = s[row * (I_DIM / GS) + (kc >> 7)];
    uint32_t o[8];
#pragma unroll
    for (int j = 0; j < 4; ++j) {
        int4 v = src[j];
        o[j * 2 + 0] = h2u(__floats2half2_rn(sc * (float)(v.x - 8), sc * (float)(v.y - 8)));
        o[j * 2 + 1] = h2u(__floats2half2_rn(sc * (float)(v.z - 8), sc * (float)(v.w - 8)));
    }
    uint4* dst = (uint4*)(g_wd + (size_t)row * I_DIM + kc);
    dst[0] = make_uint4(o[0], o[1], o[2], o[3]);
    dst[1] = make_uint4(o[4], o[5], o[6], o[7]);
}

// =================================================================
// GEMM1: g_x @ g_wgu^T, fused SwiGLU -> g_act.
// BM=128, BN=64 gate + 64 up, BK=64, 2-stage cp.async.
// 8 warps: 4(m) x 2(n). grid (16, 22, 8), m fastest.
// =================================================================
__global__ __launch_bounds__(256, 2) void gemm1_kernel() {
    const int e   = blockIdx.z;
    const int cnt = g_cnt[e];
    const int m0  = blockIdx.x * BM;
    if (m0 >= cnt) return;
    const int n0  = blockIdx.y * 64;

    extern __shared__ __half smem[];
    const uint32_t sbase = smem_u32(smem);

    const int tid = threadIdx.x, lane = tid & 31, wid = tid >> 5;
    const int warp_m = wid & 3, warp_n = wid >> 2;

    // ---- cp.async sources/dests (row fixed per thread, k advances) ----
    const int rb = tid >> 3, ch = tid & 7;   // 32 rows per pass, 8 chunks/row
    const __half* asrc[4];
    const __half* bsrc[4];
    uint32_t adst[4], bdst[4];
    const int* tokp = g_tok + e * T_TOK;
#pragma unroll
    for (int p = 0; p < 4; ++p) {
        int r = rb + p * 32;
        int m = m0 + r; if (m >= cnt) m = cnt - 1;
        asrc[p] = g_x + (size_t)tokp[m] * H_DIM + ch * 8;
        int grow = (r < 64) ? (n0 + r) : (I_DIM + n0 + r - 64);
        bsrc[p] = g_wgu + ((size_t)e * 2 * I_DIM + grow) * H_DIM + ch * 8;
        adst[p] = sbase + (uint32_t)((r * LDSW + ch * 8) * 2);
        bdst[p] = adst[p] + A_OFF * 2;
    }

    float accg[2][4][4], accu[2][4][4];
#pragma unroll
    for (int a = 0; a < 2; ++a)
#pragma unroll
        for (int b = 0; b < 4; ++b)
#pragma unroll
            for (int c = 0; c < 4; ++c) { accg[a][b][c] = 0.f; accu[a][b][c] = 0.f; }

    const int arow0 = warp_m * 32 + (lane & 15);
    const int acol  = (lane >> 4) * 8;
    const int brow  = (lane & 7) + ((lane >> 4) << 3);
    const int bcol  = ((lane >> 3) & 1) * 8;

    // prologue
#pragma unroll
    for (int p = 0; p < 4; ++p) { cp16(adst[p], asrc[p]); cp16(bdst[p], bsrc[p]); }
    CP_COMMIT();

    const int ITERS = H_DIM / BK;   // 32
    for (int it = 0; it < ITERS; ++it) {
        const int cur = it & 1;
        if (it + 1 < ITERS) {
            const uint32_t so = (uint32_t)((cur ^ 1) * STAGE_HALVES * 2);
            const int kb = (it + 1) * BK;
#pragma unroll
            for (int p = 0; p < 4; ++p) {
                cp16(adst[p] + so, asrc[p] + kb);
                cp16(bdst[p] + so, bsrc[p] + kb);
            }
            CP_COMMIT();
            CP_WAIT(1);
        } else {
            CP_WAIT(0);
        }
        __syncthreads();

        const uint32_t sa = sbase + (uint32_t)(cur * STAGE_HALVES * 2);
        const uint32_t sb = sa + A_OFF * 2;
#pragma unroll
        for (int ks = 0; ks < 4; ++ks) {
            const int kc = ks * 16;
            uint32_t A[2][4], Bg[2][4], Bu[2][4];
            ldm_x4(A[0], sa + (uint32_t)(((arow0     ) * LDSW + kc + acol) * 2));
            ldm_x4(A[1], sa + (uint32_t)(((arow0 + 16) * LDSW + kc + acol) * 2));
#pragma unroll
            for (int bb = 0; bb < 2; ++bb) {
                ldm_x4(Bg[bb], sb + (uint32_t)(((warp_n * 32 + bb * 16 + brow) * LDSW + kc + bcol) * 2));
                ldm_x4(Bu[bb], sb + (uint32_t)(((64 + warp_n * 32 + bb * 16 + brow) * LDSW + kc + bcol) * 2));
            }
#pragma unroll
            for (int mf = 0; mf < 2; ++mf)
#pragma unroll
                for (int nf = 0; nf < 4; ++nf) {
                    mma16816(accg[mf][nf], A[mf], &Bg[nf >> 1][(nf & 1) * 2]);
                    mma16816(accu[mf][nf], A[mf], &Bu[nf >> 1][(nf & 1) * 2]);
                }
        }
        __syncthreads();
    }

    // ---- epilogue: SwiGLU -> g_act ----
#pragma unroll
    for (int mf = 0; mf < 2; ++mf) {
#pragma unroll
        for (int hr = 0; hr < 2; ++hr) {
            const int m = m0 + warp_m * 32 + mf * 16 + (lane >> 2) + hr * 8;
            if (m >= cnt) continue;
            __half* arow = g_act + ((size_t)e * T_TOK + m) * I_DIM;
#pragma unroll
            for (int nf = 0; nf < 4; ++nf) {
                const int c = n0 + warp_n * 32 + nf * 8 + (lane & 3) * 2;
                const float g0 = accg[mf][nf][hr * 2 + 0];
                const float g1 = accg[mf][nf][hr * 2 + 1];
                const float u0 = accu[mf][nf][hr * 2 + 0];
                const float u1 = accu[mf][nf][hr * 2 + 1];
                const float a0 = g0 / (1.0f + __expf(-g0)) * u0;
                const float a1 = g1 / (1.0f + __expf(-g1)) * u1;
                *(__half2*)&arow[c] = __floats2half2_rn(a0, a1);
            }
        }
    }
}

// =================================================================
// GEMM2: g_act @ g_wd^T, route-weighted atomicAdd into out.
// BM=128, BN=128, BK=64, 2-stage cp.async. 8 warps: 4(m) x 2(n64).
// grid (16, 16, 8), m fastest.
// =================================================================
__global__ __launch_bounds__(256, 2) void gemm2_kernel(float* __restrict__ out) {
    const int e   = blockIdx.z;
    const int cnt = g_cnt[e];
    const int m0  = blockIdx.x * BM;
    if (m0 >= cnt) return;
    const int n0  = blockIdx.y * 128;

    extern __shared__ __half smem[];
    const uint32_t sbase = smem_u32(smem);

    const int tid = threadIdx.x, lane = tid & 31, wid = tid >> 5;
    const int warp_m = wid & 3, warp_n = wid >> 2;

    const int rb = tid >> 3, ch = tid & 7;
    const __half* asrc[4];
    const __half* bsrc[4];
    uint32_t adst[4], bdst[4];
#pragma unroll
    for (int p = 0; p < 4; ++p) {
        int r = rb + p * 32;
        int m = m0 + r; if (m >= cnt) m = cnt - 1;
        asrc[p] = g_act + ((size_t)e * T_TOK + m) * I_DIM + ch * 8;
        bsrc[p] = g_wd + ((size_t)e * H_DIM + n0 + r) * I_DIM + ch * 8;
        adst[p] = sbase + (uint32_t)((r * LDSW + ch * 8) * 2);
        bdst[p] = adst[p] + A_OFF * 2;
    }

    float acc[2][8][4];
#pragma unroll
    for (int a = 0; a < 2; ++a)
#pragma unroll
        for (int b = 0; b < 8; ++b)
#pragma unroll
            for (int c = 0; c < 4; ++c) acc[a][b][c] = 0.f;

    const int arow0 = warp_m * 32 + (lane & 15);
    const int acol  = (lane >> 4) * 8;
    const int brow  = (lane & 7) + ((lane >> 4) << 3);
    const int bcol  = ((lane >> 3) & 1) * 8;

#pragma unroll
    for (int p = 0; p < 4; ++p) { cp16(adst[p], asrc[p]); cp16(bdst[p], bsrc[p]); }
    CP_COMMIT();

    const int ITERS = I_DIM / BK;   // 22
    for (int it = 0; it < ITERS; ++it) {
        const int cur = it & 1;
        if (it + 1 < ITERS) {
            const uint32_t so = (uint32_t)((cur ^ 1) * STAGE_HALVES * 2);
            const int kb = (it + 1) * BK;
#pragma unroll
            for (int p = 0; p < 4; ++p) {
                cp16(adst[p] + so, asrc[p] + kb);
                cp16(bdst[p] + so, bsrc[p] + kb);
            }
            CP_COMMIT();
            CP_WAIT(1);
        } else {
            CP_WAIT(0);
        }
        __syncthreads();

        const uint32_t sa = sbase + (uint32_t)(cur * STAGE_HALVES * 2);
        const uint32_t sb = sa + A_OFF * 2;
#pragma unroll
        for (int ks = 0; ks < 4; ++ks) {
            const int kc = ks * 16;
            uint32_t A[2][4], B[4][4];
            ldm_x4(A[0], sa + (uint32_t)(((arow0     ) * LDSW + kc + acol) * 2));
            ldm_x4(A[1], sa + (uint32_t)(((arow0 + 16) * LDSW + kc + acol) * 2));
#pragma unroll
            for (int bb = 0; bb < 4; ++bb)
                ldm_x4(B[bb], sb + (uint32_t)(((warp_n * 64 + bb * 16 + brow) * LDSW + kc + bcol) * 2));
#pragma unroll
            for (int mf = 0; mf < 2; ++mf)
#pragma unroll
                for (int nf = 0; nf < 8; ++nf)
                    mma16816(acc[mf][nf], A[mf], &B[nf >> 1][(nf & 1) * 2]);
        }
        __syncthreads();
    }

    // ---- epilogue: route-weighted scatter-add ----
#pragma unroll
    for (int mf = 0; mf < 2; ++mf) {
#pragma unroll
        for (int hr = 0; hr < 2; ++hr) {
            const int m = m0 + warp_m * 32 + mf * 16 + (lane >> 2) + hr * 8;
            if (m >= cnt) continue;
            const int   tok = g_tok[e * T_TOK + m];
            const float rw  = g_rw [e * T_TOK + m];
            float* orow = out + (size_t)tok * H_DIM;
#pragma unroll
            for (int nf = 0; nf < 8; ++nf) {
                const int c = n0 + warp_n * 64 + nf * 8 + (lane & 3) * 2;
                atomicAdd(&orow[c],     rw * acc[mf][nf][hr * 2 + 0]);
                atomicAdd(&orow[c + 1], rw * acc[mf][nf][hr * 2 + 1]);
            }
        }
    }
}

// ---------------------------------------------------------------
extern "C" void kernel_launch(void* const* d_in, const int* in_sizes, int n_in,
                              void* d_out, int out_size) {
    const float* logits = (const float*)d_in[0];
    const float* x      = (const float*)d_in[1];
    const int*   qgu    = (const int*)  d_in[2];
    const float* sgu    = (const float*)d_in[3];
    const int*   qd     = (const int*)  d_in[4];
    const float* sd     = (const float*)d_in[5];
    float* out = (float*)d_out;

    cudaFuncSetAttribute(gemm1_kernel, cudaFuncAttributeMaxDynamicSharedMemorySize, SMEM_BYTES);
    cudaFuncSetAttribute(gemm2_kernel, cudaFuncAttributeMaxDynamicSharedMemorySize, SMEM_BYTES);

    const int n_out = T_TOK * H_DIM;
    zero_kernel<<<(n_out + 255) / 256, 256>>>(out, n_out);
    route_kernel<<<(T_TOK + 127) / 128, 128>>>(logits);
    convert_x_kernel<<<2048, 256>>>(x);
    dequant_gu_kernel<<<11264, 256>>>(qgu, sgu);
    dequant_dn_kernel<<<5632, 256>>>(qd, sd);

    dim3 g1(T_TOK / BM, I_DIM / 64, NE);    // (16, 22, 8)
    gemm1_kernel<<<g1, 256, SMEM_BYTES>>>();

    dim3 g2(T_TOK / BM, H_DIM / 128, NE);   // (16, 16, 8)
    gemm2_kernel<<<g2, 256, SMEM_BYTES>>>(out);
}

// round 9
// speedup vs baseline: 6.0394x; 1.0109x over previous
#include <cuda_runtime.h>
#include <cuda_fp16.h>
#include <stdint.h>
#include <string.h>

#define T_TOK 2048
#define H_DIM 2048
#define I_DIM 1408
#define NE    8
#define GS    128
#define BM    128
#define BK    64
#define LDSW  72                        // smem row stride in halves (144B)
#define A_OFF_B   (128 * LDSW * 2)      // B tile byte offset within a stage
#define STAGE_B   (2 * 128 * LDSW * 2)  // bytes per stage (A + B tiles)
#define NSTAGE    3
#define SMEM_BYTES (NSTAGE * STAGE_B)   // 110592 B

// ---- persistent device scratch (no runtime allocation) ----
__device__ int    g_cnt[NE];
__device__ int    g_tok[NE * T_TOK];
__device__ float  g_rw [NE * T_TOK];
__device__ __half g_x  [(size_t)T_TOK * H_DIM];
__device__ __half g_act[(size_t)NE * T_TOK * I_DIM];
__device__ __half g_wgu[(size_t)NE * 2 * I_DIM * H_DIM];  // 92 MB fp16 dequant
__device__ __half g_wd [(size_t)NE * H_DIM * I_DIM];      // 46 MB fp16 dequant

// ---------------- helpers ----------------
__device__ __forceinline__ uint32_t h2u(__half2 h) { uint32_t u; memcpy(&u, &h, 4); return u; }
__device__ __forceinline__ uint32_t smem_u32(const void* p) {
    uint32_t a;
    asm("{ .reg .u64 t; cvta.to.shared.u64 t, %1; cvt.u32.u64 %0, t; }" : "=r"(a) : "l"(p));
    return a;
}
__device__ __forceinline__ void ldm_x4(uint32_t* r, uint32_t addr) {
    asm volatile("ldmatrix.sync.aligned.m8n8.x4.shared.b16 {%0,%1,%2,%3}, [%4];"
        : "=r"(r[0]), "=r"(r[1]), "=r"(r[2]), "=r"(r[3]) : "r"(addr));
}
__device__ __forceinline__ void mma16816(float* d, const uint32_t* a, const uint32_t* b) {
    asm volatile("mma.sync.aligned.m16n8k16.row.col.f32.f16.f16.f32 "
        "{%0,%1,%2,%3}, {%4,%5,%6,%7}, {%8,%9}, {%0,%1,%2,%3};"
        : "+f"(d[0]), "+f"(d[1]), "+f"(d[2]), "+f"(d[3])
        : "r"(a[0]), "r"(a[1]), "r"(a[2]), "r"(a[3]), "r"(b[0]), "r"(b[1]));
}
__device__ __forceinline__ void cp16(uint32_t dst, const void* src) {
    asm volatile("cp.async.cg.shared.global [%0], [%1], 16;" :: "r"(dst), "l"(src));
}
#define CP_COMMIT()  asm volatile("cp.async.commit_group;")
#define CP_WAIT(n)   asm volatile("cp.async.wait_group %0;" :: "n"(n))

// ---------------- L0: zero output + counters ----------------
__global__ void zero_kernel(float* __restrict__ out, int n) {
    int i = blockIdx.x * blockDim.x + threadIdx.x;
    if (i < n) out[i] = 0.0f;
    if (i < NE) g_cnt[i] = 0;
}

// ---------------- L1: routing ----------------
__global__ void route_kernel(const float* __restrict__ logits) {
    int t = blockIdx.x * blockDim.x + threadIdx.x;
    if (t >= T_TOK) return;
    float v[NE];
#pragma unroll
    for (int e = 0; e < NE; ++e) v[e] = logits[t * NE + e];
    int i0 = 0;
#pragma unroll
    for (int e = 1; e < NE; ++e) if (v[e] > v[i0]) i0 = e;
    int i1 = (i0 == 0) ? 1 : 0;
#pragma unroll
    for (int e = 0; e < NE; ++e) if (e != i0 && v[e] > v[i1]) i1 = e;
    float ex = __expf(v[i1] - v[i0]);
    float w0 = 1.0f / (1.0f + ex);
    float w1 = ex * w0;
    int p0 = atomicAdd(&g_cnt[i0], 1);
    g_tok[i0 * T_TOK + p0] = t;  g_rw[i0 * T_TOK + p0] = w0;
    int p1 = atomicAdd(&g_cnt[i1], 1);
    g_tok[i1 * T_TOK + p1] = t;  g_rw[i1 * T_TOK + p1] = w1;
}

// ---------------- L2: x fp32 -> fp16 ----------------
__global__ void convert_x_kernel(const float* __restrict__ x) {
    size_t i = ((size_t)blockIdx.x * 256 + threadIdx.x) * 8;
    float4 a = *(const float4*)(x + i);
    float4 b = *(const float4*)(x + i + 4);
    uint4 o;
    o.x = h2u(__floats2half2_rn(a.x, a.y));
    o.y = h2u(__floats2half2_rn(a.z, a.w));
    o.z = h2u(__floats2half2_rn(b.x, b.y));
    o.w = h2u(__floats2half2_rn(b.z, b.w));
    *(uint4*)(g_x + i) = o;
}

// ---------------- L3/L4: weight dequant (DRAM-roofline bound) ----------------
__global__ void dequant_gu_kernel(const int* __restrict__ q, const float* __restrict__ s) {
    int gid = blockIdx.x * 256 + threadIdx.x;
    int row = gid >> 7;
    int kc  = (gid & 127) << 4;
    const int4* src = (const int4*)(q + (size_t)row * H_DIM + kc);
    float sc = s[row * (H_DIM / GS) + (kc >> 7)];
    uint32_t o[8];
#pragma unroll
    for (int j = 0; j < 4; ++j) {
        int4 v = src[j];
        o[j * 2 + 0] = h2u(__floats2half2_rn(sc * (float)(v.x - 8), sc * (float)(v.y - 8)));
        o[j * 2 + 1] = h2u(__floats2half2_rn(sc * (float)(v.z - 8), sc * (float)(v.w - 8)));
    }
    uint4* dst = (uint4*)(g_wgu + (size_t)row * H_DIM + kc);
    dst[0] = make_uint4(o[0], o[1], o[2], o[3]);
    dst[1] = make_uint4(o[4], o[5], o[6], o[7]);
}

__global__ void dequant_dn_kernel(const int* __restrict__ q, const float* __restrict__ s) {
    int gid = blockIdx.x * 256 + threadIdx.x;
    int row = gid / 88;
    int kc  = (gid - row * 88) << 4;
    const int4* src = (const int4*)(q + (size_t)row * I_DIM + kc);
    float sc = s[row * (I_DIM / GS) + (kc >> 7)];
    uint32_t o[8];
#pragma unroll
    for (int j = 0; j < 4; ++j) {
        int4 v = src[j];
        o[j * 2 + 0] = h2u(__floats2half2_rn(sc * (float)(v.x - 8), sc * (float)(v.y - 8)));
        o[j * 2 + 1] = h2u(__floats2half2_rn(sc * (float)(v.z - 8), sc * (float)(v.w - 8)));
    }
    uint4* dst = (uint4*)(g_wd + (size_t)row * I_DIM + kc);
    dst[0] = make_uint4(o[0], o[1], o[2], o[3]);
    dst[1] = make_uint4(o[4], o[5], o[6], o[7]);
}

// =================================================================
// GEMM1: g_x @ g_wgu^T, fused SwiGLU -> g_act.
// BM=128, BN=64 gate + 64 up, BK=64, 3-stage cp.async, 1 barrier/slab.
// =================================================================
__global__ __launch_bounds__(256, 2) void gemm1_kernel() {
    const int e   = blockIdx.z;
    const int cnt = g_cnt[e];
    const int m0  = blockIdx.x * BM;
    if (m0 >= cnt) return;
    const int n0  = blockIdx.y * 64;

    extern __shared__ __half smem[];
    const uint32_t sbase = smem_u32(smem);

    const int tid = threadIdx.x, lane = tid & 31, wid = tid >> 5;
    const int warp_m = wid & 3, warp_n = wid >> 2;

    const int rb = tid >> 3, ch = tid & 7;
    const __half* asrc[4];
    const __half* bsrc[4];
    uint32_t adst[4], bdst[4];
    const int* tokp = g_tok + e * T_TOK;
#pragma unroll
    for (int p = 0; p < 4; ++p) {
        int r = rb + p * 32;
        int m = m0 + r; if (m >= cnt) m = cnt - 1;
        asrc[p] = g_x + (size_t)tokp[m] * H_DIM + ch * 8;
        int grow = (r < 64) ? (n0 + r) : (I_DIM + n0 + r - 64);
        bsrc[p] = g_wgu + ((size_t)e * 2 * I_DIM + grow) * H_DIM + ch * 8;
        adst[p] = (uint32_t)((r * LDSW + ch * 8) * 2);
        bdst[p] = adst[p] + A_OFF_B;
    }

    float accg[2][4][4], accu[2][4][4];
#pragma unroll
    for (int a = 0; a < 2; ++a)
#pragma unroll
        for (int b = 0; b < 4; ++b)
#pragma unroll
            for (int c = 0; c < 4; ++c) { accg[a][b][c] = 0.f; accu[a][b][c] = 0.f; }

    const int arow0 = warp_m * 32 + (lane & 15);
    const int acol  = (lane >> 4) * 8;
    const int brow  = (lane & 7) + ((lane >> 4) << 3);
    const int bcol  = ((lane >> 3) & 1) * 8;

    const int S = H_DIM / BK;   // 32
    // prologue: stages 0,1
#pragma unroll
    for (int s = 0; s < 2; ++s) {
        const uint32_t stg = sbase + (uint32_t)(s * STAGE_B);
        const int kb = s * BK;
#pragma unroll
        for (int p = 0; p < 4; ++p) {
            cp16(stg + adst[p], asrc[p] + kb);
            cp16(stg + bdst[p], bsrc[p] + kb);
        }
        CP_COMMIT();
    }

    int buf = 0;
    for (int s = 0; s < S; ++s) {
        CP_WAIT(1);
        __syncthreads();
        if (s + 2 < S) {
            int nb = buf + 2; if (nb >= NSTAGE) nb -= NSTAGE;
            const uint32_t stg = sbase + (uint32_t)(nb * STAGE_B);
            const int kb = (s + 2) * BK;
#pragma unroll
            for (int p = 0; p < 4; ++p) {
                cp16(stg + adst[p], asrc[p] + kb);
                cp16(stg + bdst[p], bsrc[p] + kb);
            }
        }
        CP_COMMIT();

        const uint32_t sa = sbase + (uint32_t)(buf * STAGE_B);
        const uint32_t sb = sa + A_OFF_B;
#pragma unroll
        for (int ks = 0; ks < 4; ++ks) {
            const int kc = ks * 16;
            uint32_t A[2][4], Bg[2][4], Bu[2][4];
            ldm_x4(A[0], sa + (uint32_t)(((arow0     ) * LDSW + kc + acol) * 2));
            ldm_x4(A[1], sa + (uint32_t)(((arow0 + 16) * LDSW + kc + acol) * 2));
#pragma unroll
            for (int bb = 0; bb < 2; ++bb) {
                ldm_x4(Bg[bb], sb + (uint32_t)(((warp_n * 32 + bb * 16 + brow) * LDSW + kc + bcol) * 2));
                ldm_x4(Bu[bb], sb + (uint32_t)(((64 + warp_n * 32 + bb * 16 + brow) * LDSW + kc + bcol) * 2));
            }
#pragma unroll
            for (int mf = 0; mf < 2; ++mf)
#pragma unroll
                for (int nf = 0; nf < 4; ++nf) {
                    mma16816(accg[mf][nf], A[mf], &Bg[nf >> 1][(nf & 1) * 2]);
                    mma16816(accu[mf][nf], A[mf], &Bu[nf >> 1][(nf & 1) * 2]);
                }
        }
        if (++buf == NSTAGE) buf = 0;
    }

    // ---- epilogue: SwiGLU -> g_act ----
#pragma unroll
    for (int mf = 0; mf < 2; ++mf) {
#pragma unroll
        for (int hr = 0; hr < 2; ++hr) {
            const int m = m0 + warp_m * 32 + mf * 16 + (lane >> 2) + hr * 8;
            if (m >= cnt) continue;
            __half* arow = g_act + ((size_t)e * T_TOK + m) * I_DIM;
#pragma unroll
            for (int nf = 0; nf < 4; ++nf) {
                const int c = n0 + warp_n * 32 + nf * 8 + (lane & 3) * 2;
                const float g0 = accg[mf][nf][hr * 2 + 0];
                const float g1 = accg[mf][nf][hr * 2 + 1];
                const float u0 = accu[mf][nf][hr * 2 + 0];
                const float u1 = accu[mf][nf][hr * 2 + 1];
                const float a0 = g0 / (1.0f + __expf(-g0)) * u0;
                const float a1 = g1 / (1.0f + __expf(-g1)) * u1;
                *(__half2*)&arow[c] = __floats2half2_rn(a0, a1);
            }
        }
    }
}

// =================================================================
// GEMM2: g_act @ g_wd^T, route-weighted atomicAdd into out.
// BM=128, BN=128, BK=64, 3-stage cp.async, 1 barrier/slab.
// =================================================================
__global__ __launch_bounds__(256, 2) void gemm2_kernel(float* __restrict__ out) {
    const int e   = blockIdx.z;
    const int cnt = g_cnt[e];
    const int m0  = blockIdx.x * BM;
    if (m0 >= cnt) return;
    const int n0  = blockIdx.y * 128;

    extern __shared__ __half smem[];
    const uint32_t sbase = smem_u32(smem);

    const int tid = threadIdx.x, lane = tid & 31, wid = tid >> 5;
    const int warp_m = wid & 3, warp_n = wid >> 2;

    const int rb = tid >> 3, ch = tid & 7;
    const __half* asrc[4];
    const __half* bsrc[4];
    uint32_t adst[4], bdst[4];
#pragma unroll
    for (int p = 0; p < 4; ++p) {
        int r = rb + p * 32;
        int m = m0 + r; if (m >= cnt) m = cnt - 1;
        asrc[p] = g_act + ((size_t)e * T_TOK + m) * I_DIM + ch * 8;
        bsrc[p] = g_wd + ((size_t)e * H_DIM + n0 + r) * I_DIM + ch * 8;
        adst[p] = (uint32_t)((r * LDSW + ch * 8) * 2);
        bdst[p] = adst[p] + A_OFF_B;
    }

    float acc[2][8][4];
#pragma unroll
    for (int a = 0; a < 2; ++a)
#pragma unroll
        for (int b = 0; b < 8; ++b)
#pragma unroll
            for (int c = 0; c < 4; ++c) acc[a][b][c] = 0.f;

    const int arow0 = warp_m * 32 + (lane & 15);
    const int acol  = (lane >> 4) * 8;
    const int brow  = (lane & 7) + ((lane >> 4) << 3);
    const int bcol  = ((lane >> 3) & 1) * 8;

    const int S = I_DIM / BK;   // 22
#pragma unroll
    for (int s = 0; s < 2; ++s) {
        const uint32_t stg = sbase + (uint32_t)(s * STAGE_B);
        const int kb = s * BK;
#pragma unroll
        for (int p = 0; p < 4; ++p) {
            cp16(stg + adst[p], asrc[p] + kb);
            cp16(stg + bdst[p], bsrc[p] + kb);
        }
        CP_COMMIT();
    }

    int buf = 0;
    for (int s = 0; s < S; ++s) {
        CP_WAIT(1);
        __syncthreads();
        if (s + 2 < S) {
            int nb = buf + 2; if (nb >= NSTAGE) nb -= NSTAGE;
            const uint32_t stg = sbase + (uint32_t)(nb * STAGE_B);
            const int kb = (s + 2) * BK;
#pragma unroll
            for (int p = 0; p < 4; ++p) {
                cp16(stg + adst[p], asrc[p] + kb);
                cp16(stg + bdst[p], bsrc[p] + kb);
            }
        }
        CP_COMMIT();

        const uint32_t sa = sbase + (uint32_t)(buf * STAGE_B);
        const uint32_t sb = sa + A_OFF_B;
#pragma unroll
        for (int ks = 0; ks < 4; ++ks) {
            const int kc = ks * 16;
            uint32_t A[2][4], B[4][4];
            ldm_x4(A[0], sa + (uint32_t)(((arow0     ) * LDSW + kc + acol) * 2));
            ldm_x4(A[1], sa + (uint32_t)(((arow0 + 16) * LDSW + kc + acol) * 2));
#pragma unroll
            for (int bb = 0; bb < 4; ++bb)
                ldm_x4(B[bb], sb + (uint32_t)(((warp_n * 64 + bb * 16 + brow) * LDSW + kc + bcol) * 2));
#pragma unroll
            for (int mf = 0; mf < 2; ++mf)
#pragma unroll
                for (int nf = 0; nf < 8; ++nf)
                    mma16816(acc[mf][nf], A[mf], &B[nf >> 1][(nf & 1) * 2]);
        }
        if (++buf == NSTAGE) buf = 0;
    }

    // ---- epilogue: route-weighted scatter-add ----
#pragma unroll
    for (int mf = 0; mf < 2; ++mf) {
#pragma unroll
        for (int hr = 0; hr < 2; ++hr) {
            const int m = m0 + warp_m * 32 + mf * 16 + (lane >> 2) + hr * 8;
            if (m >= cnt) continue;
            const int   tok = g_tok[e * T_TOK + m];
            const float rw  = g_rw [e * T_TOK + m];
            float* orow = out + (size_t)tok * H_DIM;
#pragma unroll
            for (int nf = 0; nf < 8; ++nf) {
                const int c = n0 + warp_n * 64 + nf * 8 + (lane & 3) * 2;
                atomicAdd(&orow[c],     rw * acc[mf][nf][hr * 2 + 0]);
                atomicAdd(&orow[c + 1], rw * acc[mf][nf][hr * 2 + 1]);
            }
        }
    }
}

// ---------------------------------------------------------------
extern "C" void kernel_launch(void* const* d_in, const int* in_sizes, int n_in,
                              void* d_out, int out_size) {
    const float* logits = (const float*)d_in[0];
    const float* x      = (const float*)d_in[1];
    const int*   qgu    = (const int*)  d_in[2];
    const float* sgu    = (const float*)d_in[3];
    const int*   qd     = (const int*)  d_in[4];
    const float* sd     = (const float*)d_in[5];
    float* out = (float*)d_out;

    cudaFuncSetAttribute(gemm1_kernel, cudaFuncAttributeMaxDynamicSharedMemorySize, SMEM_BYTES);
    cudaFuncSetAttribute(gemm2_kernel, cudaFuncAttributeMaxDynamicSharedMemorySize, SMEM_BYTES);

    const int n_out = T_TOK * H_DIM;
    zero_kernel<<<(n_out + 255) / 256, 256>>>(out, n_out);
    route_kernel<<<(T_TOK + 127) / 128, 128>>>(logits);
    convert_x_kernel<<<2048, 256>>>(x);
    dequant_gu_kernel<<<11264, 256>>>(qgu, sgu);
    dequant_dn_kernel<<<5632, 256>>>(qd, sd);

    dim3 g1(T_TOK / BM, I_DIM / 64, NE);    // (16, 22, 8)
    gemm1_kernel<<<g1, 256, SMEM_BYTES>>>();

    dim3 g2(T_TOK / BM, H_DIM / 128, NE);   // (16, 16, 8)
    gemm2_kernel<<<g2, 256, SMEM_BYTES>>>(out);
}